// round 6
// baseline (speedup 1.0000x reference)
#include <cuda_runtime.h>
#include <cstdint>

#define N_NODES 50000
#define N_EDGES 800000
#define FEATS   512
#define N_ELEMS (N_NODES * FEATS)
#define M_TILES 391                 // ceil(50000/128)
#define PAD_ROWS (M_TILES * 128)    // 50048

// Scratch (device globals — no cudaMalloc allowed). Zero-initialized at load;
// pad rows of g_agg are never written, so they stay zero.
__device__ float g_xd [(size_t)N_NODES * FEATS];
__device__ float g_agg[(size_t)PAD_ROWS * FEATS];
__device__ float g_Wt [(size_t)FEATS * FEATS];      // W^T, tf32-rounded: Wt[n][k]
__device__ int   g_rowptr[N_NODES + 1];

// ---------------------------------------------------------------------------
// helpers
// ---------------------------------------------------------------------------
__device__ __forceinline__ uint32_t smem_u32(const void* p) {
    uint32_t a;
    asm("{ .reg .u64 t; cvta.to.shared.u64 t, %1; cvt.u32.u64 %0, t; }" : "=r"(a) : "l"(p));
    return a;
}
__device__ __forceinline__ void cp_async16(uint32_t dst, const void* src) {
    asm volatile("cp.async.cg.shared.global [%0], [%1], 16;" :: "r"(dst), "l"(src));
}
__device__ __forceinline__ void cp_commit() {
    asm volatile("cp.async.commit_group;" ::: "memory");
}
template <int N>
__device__ __forceinline__ void cp_wait() {
    asm volatile("cp.async.wait_group %0;" :: "n"(N) : "memory");
}
__device__ __forceinline__ float tf32_rn(float v) {
    uint32_t r;
    asm("cvt.rn.tf32.f32 %0, %1;" : "=r"(r) : "f"(v));
    return __uint_as_float(r);
}
// D = A(16x8 tf32, row) * B(8x8 tf32, col) + D, fp32 accum
__device__ __forceinline__ void mma_tf32(float* c, const uint32_t* a, const uint32_t* b) {
    asm volatile(
        "mma.sync.aligned.m16n8k8.row.col.f32.tf32.tf32.f32 "
        "{%0,%1,%2,%3}, {%4,%5,%6,%7}, {%8,%9}, {%0,%1,%2,%3};"
        : "+f"(c[0]), "+f"(c[1]), "+f"(c[2]), "+f"(c[3])
        : "r"(a[0]), "r"(a[1]), "r"(a[2]), "r"(a[3]), "r"(b[0]), "r"(b[1]));
}

// ---------------------------------------------------------------------------
// Kernel 0a: Wt[n][k] = tf32_rn(W[k][n])
// ---------------------------------------------------------------------------
__global__ void transpose_W_kernel(const float* __restrict__ W) {
    __shared__ float t[32][33];
    const int tx = threadIdx.x, ty = threadIdx.y;          // 32 x 8
    const int bx = blockIdx.x, by = blockIdx.y;
    const int x = bx * 32 + tx;
#pragma unroll
    for (int i = 0; i < 4; i++) {
        const int y = by * 32 + ty + i * 8;
        t[ty + i * 8][tx] = W[(size_t)y * 512 + x];
    }
    __syncthreads();
    const int x2 = by * 32 + tx;                           // k
#pragma unroll
    for (int i = 0; i < 4; i++) {
        const int y2 = bx * 32 + ty + i * 8;               // n
        g_Wt[(size_t)y2 * 512 + x2] = tf32_rn(t[tx][ty + i * 8]);
    }
}

// ---------------------------------------------------------------------------
// Kernel 0b: row_ptr from sorted edge_dst. row_ptr[n] = first e with dst >= n.
// ---------------------------------------------------------------------------
__global__ void rowptr_kernel(const int* __restrict__ edge_dst) {
    const int e = blockIdx.x * blockDim.x + threadIdx.x;
    if (e > N_EDGES) return;
    const int d_prev = (e == 0)       ? -1      : __ldcs(edge_dst + e - 1);
    const int d_cur  = (e == N_EDGES) ? N_NODES : __ldcs(edge_dst + e);
    for (int n = d_prev + 1; n <= d_cur; n++) g_rowptr[n] = e;
}

// ---------------------------------------------------------------------------
// Kernel 1: dropout, JAX partitionable threefry-2x32-20.
// ---------------------------------------------------------------------------
__device__ __forceinline__ unsigned rotl32(unsigned x, int d) {
    return (x << d) | (x >> (32 - d));
}
__device__ __forceinline__ unsigned threefry_elem(unsigned i) {
    const unsigned ks0 = 0u, ks1 = 42u;
    const unsigned ks2 = ks0 ^ ks1 ^ 0x1BD11BDAu;
    unsigned x0 = 0u, x1 = i;
    x0 += ks0; x1 += ks1;
#define TF_ROUND(r) { x0 += x1; x1 = rotl32(x1, (r)); x1 ^= x0; }
    TF_ROUND(13) TF_ROUND(15) TF_ROUND(26) TF_ROUND(6)
    x0 += ks1; x1 += ks2 + 1u;
    TF_ROUND(17) TF_ROUND(29) TF_ROUND(16) TF_ROUND(24)
    x0 += ks2; x1 += ks0 + 2u;
    TF_ROUND(13) TF_ROUND(15) TF_ROUND(26) TF_ROUND(6)
    x0 += ks0; x1 += ks1 + 3u;
    TF_ROUND(17) TF_ROUND(29) TF_ROUND(16) TF_ROUND(24)
    x0 += ks1; x1 += ks2 + 4u;
    TF_ROUND(13) TF_ROUND(15) TF_ROUND(26) TF_ROUND(6)
    x0 += ks2; x1 += ks0 + 5u;
#undef TF_ROUND
    return x0 ^ x1;
}

__global__ void dropout_kernel(const float* __restrict__ x) {
    const unsigned base = (blockIdx.x * blockDim.x + threadIdx.x) * 4u;
    if (base >= (unsigned)N_ELEMS) return;
    const float4 v = __ldcs(reinterpret_cast<const float4*>(x + base));
    const float inv_keep = 1.0f / 0.9f;
    unsigned b0 = threefry_elem(base + 0u);
    unsigned b1 = threefry_elem(base + 1u);
    unsigned b2 = threefry_elem(base + 2u);
    unsigned b3 = threefry_elem(base + 3u);
    float u0 = __uint_as_float((b0 >> 9) | 0x3f800000u) - 1.0f;
    float u1 = __uint_as_float((b1 >> 9) | 0x3f800000u) - 1.0f;
    float u2 = __uint_as_float((b2 >> 9) | 0x3f800000u) - 1.0f;
    float u3 = __uint_as_float((b3 >> 9) | 0x3f800000u) - 1.0f;
    float4 o;
    o.x = (u0 < 0.9f) ? v.x * inv_keep : 0.0f;
    o.y = (u1 < 0.9f) ? v.y * inv_keep : 0.0f;
    o.z = (u2 < 0.9f) ? v.z * inv_keep : 0.0f;
    o.w = (u3 < 0.9f) ? v.w * inv_keep : 0.0f;
    *reinterpret_cast<float4*>(g_xd + base) = o;
}

// ---------------------------------------------------------------------------
// Kernel 2: segment-sum aggregation, row_ptr ranges, unroll x8 for MLP.
// Streaming hints: edge arrays evict-first, g_agg write streaming so g_xd
// stays L2-resident. tf32-round result.
// ---------------------------------------------------------------------------
__global__ void agg_kernel(const float* __restrict__ edge_w,
                           const int*   __restrict__ edge_src) {
    const int node = blockIdx.x;
    const int start = g_rowptr[node];
    const int end   = g_rowptr[node + 1];

    const int f = threadIdx.x;
    float4 acc = make_float4(0.f, 0.f, 0.f, 0.f);

    int e = start;
#pragma unroll 1
    for (; e + 8 <= end; e += 8) {
        float w[8]; int s[8];
#pragma unroll
        for (int u = 0; u < 8; u++) { w[u] = __ldcs(edge_w + e + u); s[u] = __ldcs(edge_src + e + u); }
        float4 v[8];
#pragma unroll
        for (int u = 0; u < 8; u++)
            v[u] = reinterpret_cast<const float4*>(g_xd + (size_t)s[u] * FEATS)[f];
#pragma unroll
        for (int u = 0; u < 8; u++) {
            acc.x += w[u] * v[u].x; acc.y += w[u] * v[u].y;
            acc.z += w[u] * v[u].z; acc.w += w[u] * v[u].w;
        }
    }
#pragma unroll 1
    for (; e + 4 <= end; e += 4) {
        float w[4]; int s[4];
#pragma unroll
        for (int u = 0; u < 4; u++) { w[u] = __ldcs(edge_w + e + u); s[u] = __ldcs(edge_src + e + u); }
        float4 v[4];
#pragma unroll
        for (int u = 0; u < 4; u++)
            v[u] = reinterpret_cast<const float4*>(g_xd + (size_t)s[u] * FEATS)[f];
#pragma unroll
        for (int u = 0; u < 4; u++) {
            acc.x += w[u] * v[u].x; acc.y += w[u] * v[u].y;
            acc.z += w[u] * v[u].z; acc.w += w[u] * v[u].w;
        }
    }
#pragma unroll 1
    for (; e < end; e++) {
        const float w = __ldcs(edge_w + e);
        const int   s = __ldcs(edge_src + e);
        const float4 v = reinterpret_cast<const float4*>(g_xd + (size_t)s * FEATS)[f];
        acc.x += w * v.x; acc.y += w * v.y; acc.z += w * v.z; acc.w += w * v.w;
    }
    float4 r;
    r.x = tf32_rn(acc.x); r.y = tf32_rn(acc.y); r.z = tf32_rn(acc.z); r.w = tf32_rn(acc.w);
    __stcs(reinterpret_cast<float4*>(g_agg + (size_t)node * FEATS) + f, r);
}

// ---------------------------------------------------------------------------
// Kernel 3: mma.sync tf32 GEMM. out = relu(agg @ Wt^T + b).
// 128x128 CTA tile, 4 warps, 64x64 warp tiles (LDS:mma = 1.0), BK=32,
// 2-stage cp.async (dynamic smem 72 KB), one barrier per K-iter.
// ---------------------------------------------------------------------------
#define BK 32
#define LDP 36                         // padded row stride (floats)
#define STAGE_F (128 * LDP)            // floats per stage per matrix
#define GEMM_SMEM_BYTES (4 * STAGE_F * 4)   // A0,A1,B0,B1

__global__ void __launch_bounds__(128, 2)
gemm_mma_kernel(const float* __restrict__ bias, float* __restrict__ out) {
    extern __shared__ float sm[];
    float* Asm = sm;                    // [2][128][LDP]
    float* Bsm = sm + 2 * STAGE_F;      // [2][128][LDP]

    const int tid   = threadIdx.x;
    const int wid   = tid >> 5;
    const int lane  = tid & 31;
    const int warpM = wid & 1;          // 0..1 -> M offset 0/64
    const int warpN = wid >> 1;         // 0..1 -> N offset 0/64
    const int m0 = blockIdx.y * 128;
    const int n0 = blockIdx.x * 128;

    const uint32_t aBase = smem_u32(Asm);
    const uint32_t bBase = smem_u32(Bsm);
    const uint32_t stageBytes = STAGE_F * 4;

    float acc[4][8][4];
#pragma unroll
    for (int i = 0; i < 4; i++)
#pragma unroll
        for (int j = 0; j < 8; j++)
#pragma unroll
            for (int r = 0; r < 4; r++) acc[i][j][r] = 0.f;

    auto load_tile = [&](int s, int k0) {
#pragma unroll
        for (int it = 0; it < 8; it++) {
            const int idx = it * 128 + tid;            // 0..1023
            const int row = idx >> 3, seg = idx & 7;
            cp_async16(aBase + s * stageBytes + (row * LDP + seg * 4) * 4,
                       &g_agg[(size_t)(m0 + row) * 512 + k0 + seg * 4]);
        }
#pragma unroll
        for (int it = 0; it < 8; it++) {
            const int idx = it * 128 + tid;
            const int row = idx >> 3, seg = idx & 7;
            cp_async16(bBase + s * stageBytes + (row * LDP + seg * 4) * 4,
                       &g_Wt[(size_t)(n0 + row) * 512 + k0 + seg * 4]);
        }
        cp_commit();
    };

    load_tile(0, 0);

    const int qrow = lane >> 2;   // 0..7
    const int qcol = lane & 3;    // 0..3

    for (int c = 0; c < 16; c++) {
        const int s = c & 1;
        cp_wait<0>();
        __syncthreads();
        if (c + 1 < 16) load_tile(s ^ 1, (c + 1) * BK);   // overlaps mma below

        const float* As = Asm + s * STAGE_F;
        const float* Bs = Bsm + s * STAGE_F;
#pragma unroll
        for (int kk = 0; kk < 4; kk++) {
            const int kb = kk * 8;
            uint32_t af[4][4];
#pragma unroll
            for (int mt = 0; mt < 4; mt++) {
                const int r0 = warpM * 64 + mt * 16 + qrow;
                af[mt][0] = __float_as_uint(As[r0 * LDP + kb + qcol]);
                af[mt][1] = __float_as_uint(As[(r0 + 8) * LDP + kb + qcol]);
                af[mt][2] = __float_as_uint(As[r0 * LDP + kb + 4 + qcol]);
                af[mt][3] = __float_as_uint(As[(r0 + 8) * LDP + kb + 4 + qcol]);
            }
            uint32_t bf[8][2];
#pragma unroll
            for (int nt = 0; nt < 8; nt++) {
                const int rn = warpN * 64 + nt * 8 + qrow;
                bf[nt][0] = __float_as_uint(Bs[rn * LDP + kb + qcol]);
                bf[nt][1] = __float_as_uint(Bs[rn * LDP + kb + 4 + qcol]);
            }
#pragma unroll
            for (int mt = 0; mt < 4; mt++)
#pragma unroll
                for (int nt = 0; nt < 8; nt++)
                    mma_tf32(acc[mt][nt], af[mt], bf[nt]);
        }
    }

    // epilogue: bias + relu, streaming stores
#pragma unroll
    for (int mt = 0; mt < 4; mt++) {
        const int row0 = m0 + warpM * 64 + mt * 16 + qrow;
        const int row1 = row0 + 8;
#pragma unroll
        for (int nt = 0; nt < 8; nt++) {
            const int col = n0 + warpN * 64 + nt * 8 + 2 * qcol;
            const float b0 = __ldg(bias + col);
            const float b1 = __ldg(bias + col + 1);
            if (row0 < N_NODES) {
                float2 o;
                o.x = fmaxf(acc[mt][nt][0] + b0, 0.f);
                o.y = fmaxf(acc[mt][nt][1] + b1, 0.f);
                __stcs(reinterpret_cast<float2*>(out + (size_t)row0 * 512 + col), o);
            }
            if (row1 < N_NODES) {
                float2 o;
                o.x = fmaxf(acc[mt][nt][2] + b0, 0.f);
                o.y = fmaxf(acc[mt][nt][3] + b1, 0.f);
                __stcs(reinterpret_cast<float2*>(out + (size_t)row1 * 512 + col), o);
            }
        }
    }
}

// ---------------------------------------------------------------------------
// Launch
// ---------------------------------------------------------------------------
extern "C" void kernel_launch(void* const* d_in, const int* in_sizes, int n_in,
                              void* d_out, int out_size) {
    const float* x        = (const float*)d_in[0];
    const float* edge_w   = (const float*)d_in[1];
    const float* W        = (const float*)d_in[2];
    const float* b        = (const float*)d_in[3];
    const int*   edge_src = (const int*)  d_in[4];
    const int*   edge_dst = (const int*)  d_in[5];
    float* out = (float*)d_out;

    cudaFuncSetAttribute(gemm_mma_kernel,
                         cudaFuncAttributeMaxDynamicSharedMemorySize, GEMM_SMEM_BYTES);

    transpose_W_kernel<<<dim3(16, 16), dim3(32, 8)>>>(W);
    rowptr_kernel<<<(N_EDGES + 256) / 256, 256>>>(edge_dst);
    dropout_kernel<<<(N_ELEMS / 4 + 255) / 256, 256>>>(x);
    agg_kernel<<<N_NODES, 128>>>(edge_w, edge_src);
    gemm_mma_kernel<<<dim3(4, M_TILES), 128, GEMM_SMEM_BYTES>>>(b, out);
}

// round 7
// speedup vs baseline: 1.0802x; 1.0802x over previous
#include <cuda_runtime.h>
#include <cstdint>

#define N_NODES 50000
#define N_EDGES 800000
#define FEATS   512
#define N_ELEMS (N_NODES * FEATS)
#define M_TILES 391                 // ceil(50000/128)
#define PAD_ROWS (M_TILES * 128)    // 50048

// Scratch (device globals — no cudaMalloc allowed). Zero-initialized at load;
// pad rows of g_agg are never written, so they stay zero.
__device__ float g_xd [(size_t)N_NODES * FEATS];
__device__ float g_agg[(size_t)PAD_ROWS * FEATS];
__device__ float g_Wt [(size_t)FEATS * FEATS];      // W^T, tf32-rounded: Wt[n][k]
__device__ int   g_rowptr[N_NODES + 1];

// ---------------------------------------------------------------------------
// helpers
// ---------------------------------------------------------------------------
__device__ __forceinline__ uint32_t smem_u32(const void* p) {
    uint32_t a;
    asm("{ .reg .u64 t; cvta.to.shared.u64 t, %1; cvt.u32.u64 %0, t; }" : "=r"(a) : "l"(p));
    return a;
}
__device__ __forceinline__ void cp_async16(uint32_t dst, const void* src) {
    asm volatile("cp.async.cg.shared.global [%0], [%1], 16;" :: "r"(dst), "l"(src));
}
__device__ __forceinline__ void cp_commit() {
    asm volatile("cp.async.commit_group;" ::: "memory");
}
template <int N>
__device__ __forceinline__ void cp_wait() {
    asm volatile("cp.async.wait_group %0;" :: "n"(N) : "memory");
}
__device__ __forceinline__ float tf32_rn(float v) {
    uint32_t r;
    asm("cvt.rn.tf32.f32 %0, %1;" : "=r"(r) : "f"(v));
    return __uint_as_float(r);
}
// D = A(16x8 tf32, row) * B(8x8 tf32, col) + D, fp32 accum
__device__ __forceinline__ void mma_tf32(float* c, const uint32_t* a, const uint32_t* b) {
    asm volatile(
        "mma.sync.aligned.m16n8k8.row.col.f32.tf32.tf32.f32 "
        "{%0,%1,%2,%3}, {%4,%5,%6,%7}, {%8,%9}, {%0,%1,%2,%3};"
        : "+f"(c[0]), "+f"(c[1]), "+f"(c[2]), "+f"(c[3])
        : "r"(a[0]), "r"(a[1]), "r"(a[2]), "r"(a[3]), "r"(b[0]), "r"(b[1]));
}

// ---------------------------------------------------------------------------
// Kernel 0a: Wt[n][k] = tf32_rn(W[k][n])
// ---------------------------------------------------------------------------
__global__ void transpose_W_kernel(const float* __restrict__ W) {
    __shared__ float t[32][33];
    const int tx = threadIdx.x, ty = threadIdx.y;          // 32 x 8
    const int bx = blockIdx.x, by = blockIdx.y;
    const int x = bx * 32 + tx;
#pragma unroll
    for (int i = 0; i < 4; i++) {
        const int y = by * 32 + ty + i * 8;
        t[ty + i * 8][tx] = W[(size_t)y * 512 + x];
    }
    __syncthreads();
    const int x2 = by * 32 + tx;                           // k
#pragma unroll
    for (int i = 0; i < 4; i++) {
        const int y2 = bx * 32 + ty + i * 8;               // n
        g_Wt[(size_t)y2 * 512 + x2] = tf32_rn(t[tx][ty + i * 8]);
    }
}

// ---------------------------------------------------------------------------
// Kernel 0b: row_ptr from sorted edge_dst. row_ptr[n] = first e with dst >= n.
// ---------------------------------------------------------------------------
__global__ void rowptr_kernel(const int* __restrict__ edge_dst) {
    const int e = blockIdx.x * blockDim.x + threadIdx.x;
    if (e > N_EDGES) return;
    const int d_prev = (e == 0)       ? -1      : edge_dst[e - 1];
    const int d_cur  = (e == N_EDGES) ? N_NODES : edge_dst[e];
    for (int n = d_prev + 1; n <= d_cur; n++) g_rowptr[n] = e;
}

// ---------------------------------------------------------------------------
// Kernel 1: dropout, JAX partitionable threefry-2x32-20.
// ---------------------------------------------------------------------------
__device__ __forceinline__ unsigned rotl32(unsigned x, int d) {
    return (x << d) | (x >> (32 - d));
}
__device__ __forceinline__ unsigned threefry_elem(unsigned i) {
    const unsigned ks0 = 0u, ks1 = 42u;
    const unsigned ks2 = ks0 ^ ks1 ^ 0x1BD11BDAu;
    unsigned x0 = 0u, x1 = i;
    x0 += ks0; x1 += ks1;
#define TF_ROUND(r) { x0 += x1; x1 = rotl32(x1, (r)); x1 ^= x0; }
    TF_ROUND(13) TF_ROUND(15) TF_ROUND(26) TF_ROUND(6)
    x0 += ks1; x1 += ks2 + 1u;
    TF_ROUND(17) TF_ROUND(29) TF_ROUND(16) TF_ROUND(24)
    x0 += ks2; x1 += ks0 + 2u;
    TF_ROUND(13) TF_ROUND(15) TF_ROUND(26) TF_ROUND(6)
    x0 += ks0; x1 += ks1 + 3u;
    TF_ROUND(17) TF_ROUND(29) TF_ROUND(16) TF_ROUND(24)
    x0 += ks1; x1 += ks2 + 4u;
    TF_ROUND(13) TF_ROUND(15) TF_ROUND(26) TF_ROUND(6)
    x0 += ks2; x1 += ks0 + 5u;
#undef TF_ROUND
    return x0 ^ x1;
}

__global__ void dropout_kernel(const float* __restrict__ x) {
    const unsigned base = (blockIdx.x * blockDim.x + threadIdx.x) * 4u;
    if (base >= (unsigned)N_ELEMS) return;
    const float4 v = __ldcs(reinterpret_cast<const float4*>(x + base));
    const float inv_keep = 1.0f / 0.9f;
    unsigned b0 = threefry_elem(base + 0u);
    unsigned b1 = threefry_elem(base + 1u);
    unsigned b2 = threefry_elem(base + 2u);
    unsigned b3 = threefry_elem(base + 3u);
    float u0 = __uint_as_float((b0 >> 9) | 0x3f800000u) - 1.0f;
    float u1 = __uint_as_float((b1 >> 9) | 0x3f800000u) - 1.0f;
    float u2 = __uint_as_float((b2 >> 9) | 0x3f800000u) - 1.0f;
    float u3 = __uint_as_float((b3 >> 9) | 0x3f800000u) - 1.0f;
    float4 o;
    o.x = (u0 < 0.9f) ? v.x * inv_keep : 0.0f;
    o.y = (u1 < 0.9f) ? v.y * inv_keep : 0.0f;
    o.z = (u2 < 0.9f) ? v.z * inv_keep : 0.0f;
    o.w = (u3 < 0.9f) ? v.w * inv_keep : 0.0f;
    *reinterpret_cast<float4*>(g_xd + base) = o;
}

// ---------------------------------------------------------------------------
// Kernel 2: segment-sum aggregation (R5 structure: unroll x4, plain loads),
// single change: evict-first streaming store of the result so the g_agg
// write-stream doesn't evict the g_xd gather working set from L2.
// ---------------------------------------------------------------------------
__global__ void agg_kernel(const float* __restrict__ edge_w,
                           const int*   __restrict__ edge_src) {
    const int node = blockIdx.x;
    const int start = g_rowptr[node];
    const int end   = g_rowptr[node + 1];

    const int f = threadIdx.x;
    float4 acc = make_float4(0.f, 0.f, 0.f, 0.f);

    int e = start;
#pragma unroll 1
    for (; e + 4 <= end; e += 4) {
        const float w0 = edge_w[e + 0], w1 = edge_w[e + 1];
        const float w2 = edge_w[e + 2], w3 = edge_w[e + 3];
        const int   s0 = edge_src[e + 0], s1 = edge_src[e + 1];
        const int   s2 = edge_src[e + 2], s3 = edge_src[e + 3];
        const float4 v0 = reinterpret_cast<const float4*>(g_xd + (size_t)s0 * FEATS)[f];
        const float4 v1 = reinterpret_cast<const float4*>(g_xd + (size_t)s1 * FEATS)[f];
        const float4 v2 = reinterpret_cast<const float4*>(g_xd + (size_t)s2 * FEATS)[f];
        const float4 v3 = reinterpret_cast<const float4*>(g_xd + (size_t)s3 * FEATS)[f];
        acc.x += w0 * v0.x + w1 * v1.x + w2 * v2.x + w3 * v3.x;
        acc.y += w0 * v0.y + w1 * v1.y + w2 * v2.y + w3 * v3.y;
        acc.z += w0 * v0.z + w1 * v1.z + w2 * v2.z + w3 * v3.z;
        acc.w += w0 * v0.w + w1 * v1.w + w2 * v2.w + w3 * v3.w;
    }
#pragma unroll 1
    for (; e < end; e++) {
        const float w = edge_w[e];
        const int   s = edge_src[e];
        const float4 v = reinterpret_cast<const float4*>(g_xd + (size_t)s * FEATS)[f];
        acc.x += w * v.x; acc.y += w * v.y; acc.z += w * v.z; acc.w += w * v.w;
    }
    float4 r;
    r.x = tf32_rn(acc.x); r.y = tf32_rn(acc.y); r.z = tf32_rn(acc.z); r.w = tf32_rn(acc.w);
    __stcs(reinterpret_cast<float4*>(g_agg + (size_t)node * FEATS) + f, r);
}

// ---------------------------------------------------------------------------
// Kernel 3: mma.sync tf32 GEMM (R6 version — 9 us better than R5's).
// 128x128 CTA tile, 4 warps, 64x64 warp tiles (LDS:mma = 1.0), BK=32,
// 2-stage cp.async (dynamic smem 72 KB), one barrier per K-iter.
// ---------------------------------------------------------------------------
#define BK 32
#define LDP 36                         // padded row stride (floats)
#define STAGE_F (128 * LDP)            // floats per stage per matrix
#define GEMM_SMEM_BYTES (4 * STAGE_F * 4)   // A0,A1,B0,B1

__global__ void __launch_bounds__(128, 2)
gemm_mma_kernel(const float* __restrict__ bias, float* __restrict__ out) {
    extern __shared__ float sm[];
    float* Asm = sm;                    // [2][128][LDP]
    float* Bsm = sm + 2 * STAGE_F;      // [2][128][LDP]

    const int tid   = threadIdx.x;
    const int wid   = tid >> 5;
    const int lane  = tid & 31;
    const int warpM = wid & 1;          // 0..1 -> M offset 0/64
    const int warpN = wid >> 1;         // 0..1 -> N offset 0/64
    const int m0 = blockIdx.y * 128;
    const int n0 = blockIdx.x * 128;

    const uint32_t aBase = smem_u32(Asm);
    const uint32_t bBase = smem_u32(Bsm);
    const uint32_t stageBytes = STAGE_F * 4;

    float acc[4][8][4];
#pragma unroll
    for (int i = 0; i < 4; i++)
#pragma unroll
        for (int j = 0; j < 8; j++)
#pragma unroll
            for (int r = 0; r < 4; r++) acc[i][j][r] = 0.f;

    auto load_tile = [&](int s, int k0) {
#pragma unroll
        for (int it = 0; it < 8; it++) {
            const int idx = it * 128 + tid;            // 0..1023
            const int row = idx >> 3, seg = idx & 7;
            cp_async16(aBase + s * stageBytes + (row * LDP + seg * 4) * 4,
                       &g_agg[(size_t)(m0 + row) * 512 + k0 + seg * 4]);
        }
#pragma unroll
        for (int it = 0; it < 8; it++) {
            const int idx = it * 128 + tid;
            const int row = idx >> 3, seg = idx & 7;
            cp_async16(bBase + s * stageBytes + (row * LDP + seg * 4) * 4,
                       &g_Wt[(size_t)(n0 + row) * 512 + k0 + seg * 4]);
        }
        cp_commit();
    };

    load_tile(0, 0);

    const int qrow = lane >> 2;   // 0..7
    const int qcol = lane & 3;    // 0..3

    for (int c = 0; c < 16; c++) {
        const int s = c & 1;
        cp_wait<0>();
        __syncthreads();
        if (c + 1 < 16) load_tile(s ^ 1, (c + 1) * BK);   // overlaps mma below

        const float* As = Asm + s * STAGE_F;
        const float* Bs = Bsm + s * STAGE_F;
#pragma unroll
        for (int kk = 0; kk < 4; kk++) {
            const int kb = kk * 8;
            uint32_t af[4][4];
#pragma unroll
            for (int mt = 0; mt < 4; mt++) {
                const int r0 = warpM * 64 + mt * 16 + qrow;
                af[mt][0] = __float_as_uint(As[r0 * LDP + kb + qcol]);
                af[mt][1] = __float_as_uint(As[(r0 + 8) * LDP + kb + qcol]);
                af[mt][2] = __float_as_uint(As[r0 * LDP + kb + 4 + qcol]);
                af[mt][3] = __float_as_uint(As[(r0 + 8) * LDP + kb + 4 + qcol]);
            }
            uint32_t bf[8][2];
#pragma unroll
            for (int nt = 0; nt < 8; nt++) {
                const int rn = warpN * 64 + nt * 8 + qrow;
                bf[nt][0] = __float_as_uint(Bs[rn * LDP + kb + qcol]);
                bf[nt][1] = __float_as_uint(Bs[rn * LDP + kb + 4 + qcol]);
            }
#pragma unroll
            for (int mt = 0; mt < 4; mt++)
#pragma unroll
                for (int nt = 0; nt < 8; nt++)
                    mma_tf32(acc[mt][nt], af[mt], bf[nt]);
        }
    }

    // epilogue: bias + relu, streaming stores
#pragma unroll
    for (int mt = 0; mt < 4; mt++) {
        const int row0 = m0 + warpM * 64 + mt * 16 + qrow;
        const int row1 = row0 + 8;
#pragma unroll
        for (int nt = 0; nt < 8; nt++) {
            const int col = n0 + warpN * 64 + nt * 8 + 2 * qcol;
            const float b0 = __ldg(bias + col);
            const float b1 = __ldg(bias + col + 1);
            if (row0 < N_NODES) {
                float2 o;
                o.x = fmaxf(acc[mt][nt][0] + b0, 0.f);
                o.y = fmaxf(acc[mt][nt][1] + b1, 0.f);
                __stcs(reinterpret_cast<float2*>(out + (size_t)row0 * 512 + col), o);
            }
            if (row1 < N_NODES) {
                float2 o;
                o.x = fmaxf(acc[mt][nt][2] + b0, 0.f);
                o.y = fmaxf(acc[mt][nt][3] + b1, 0.f);
                __stcs(reinterpret_cast<float2*>(out + (size_t)row1 * 512 + col), o);
            }
        }
    }
}

// ---------------------------------------------------------------------------
// Launch
// ---------------------------------------------------------------------------
extern "C" void kernel_launch(void* const* d_in, const int* in_sizes, int n_in,
                              void* d_out, int out_size) {
    const float* x        = (const float*)d_in[0];
    const float* edge_w   = (const float*)d_in[1];
    const float* W        = (const float*)d_in[2];
    const float* b        = (const float*)d_in[3];
    const int*   edge_src = (const int*)  d_in[4];
    const int*   edge_dst = (const int*)  d_in[5];
    float* out = (float*)d_out;

    cudaFuncSetAttribute(gemm_mma_kernel,
                         cudaFuncAttributeMaxDynamicSharedMemorySize, GEMM_SMEM_BYTES);

    transpose_W_kernel<<<dim3(16, 16), dim3(32, 8)>>>(W);
    rowptr_kernel<<<(N_EDGES + 256) / 256, 256>>>(edge_dst);
    dropout_kernel<<<(N_ELEMS / 4 + 255) / 256, 256>>>(x);
    agg_kernel<<<N_NODES, 128>>>(edge_w, edge_src);
    gemm_mma_kernel<<<dim3(4, M_TILES), 128, GEMM_SMEM_BYTES>>>(b, out);
}

// round 8
// speedup vs baseline: 1.2574x; 1.1640x over previous
#include <cuda_runtime.h>
#include <cuda_fp16.h>
#include <cstdint>

#define N_NODES 50000
#define N_EDGES 800000
#define FEATS   512
#define N_ELEMS (N_NODES * FEATS)
#define M_TILES 391                 // ceil(50000/128)
#define PAD_ROWS (M_TILES * 128)    // 50048

// Scratch (device globals — no cudaMalloc allowed). Zero-initialized at load;
// pad rows of g_agg are never written, so they stay zero.
__device__ __half g_xd_h[(size_t)N_NODES * FEATS];   // fp16 dropout output (51 MB)
__device__ float  g_agg [(size_t)PAD_ROWS * FEATS];
__device__ float  g_Wt  [(size_t)FEATS * FEATS];     // W^T, tf32-rounded: Wt[n][k]
__device__ int    g_rowptr[N_NODES + 1];

// ---------------------------------------------------------------------------
// helpers
// ---------------------------------------------------------------------------
__device__ __forceinline__ uint32_t smem_u32(const void* p) {
    uint32_t a;
    asm("{ .reg .u64 t; cvta.to.shared.u64 t, %1; cvt.u32.u64 %0, t; }" : "=r"(a) : "l"(p));
    return a;
}
__device__ __forceinline__ void cp_async16(uint32_t dst, const void* src) {
    asm volatile("cp.async.cg.shared.global [%0], [%1], 16;" :: "r"(dst), "l"(src));
}
__device__ __forceinline__ void cp_commit() {
    asm volatile("cp.async.commit_group;" ::: "memory");
}
template <int N>
__device__ __forceinline__ void cp_wait() {
    asm volatile("cp.async.wait_group %0;" :: "n"(N) : "memory");
}
__device__ __forceinline__ float tf32_rn(float v) {
    uint32_t r;
    asm("cvt.rn.tf32.f32 %0, %1;" : "=r"(r) : "f"(v));
    return __uint_as_float(r);
}
// D = A(16x8 tf32, row) * B(8x8 tf32, col) + D, fp32 accum
__device__ __forceinline__ void mma_tf32(float* c, const uint32_t* a, const uint32_t* b) {
    asm volatile(
        "mma.sync.aligned.m16n8k8.row.col.f32.tf32.tf32.f32 "
        "{%0,%1,%2,%3}, {%4,%5,%6,%7}, {%8,%9}, {%0,%1,%2,%3};"
        : "+f"(c[0]), "+f"(c[1]), "+f"(c[2]), "+f"(c[3])
        : "r"(a[0]), "r"(a[1]), "r"(a[2]), "r"(a[3]), "r"(b[0]), "r"(b[1]));
}

// ---------------------------------------------------------------------------
// Kernel 0a: Wt[n][k] = tf32_rn(W[k][n])
// ---------------------------------------------------------------------------
__global__ void transpose_W_kernel(const float* __restrict__ W) {
    __shared__ float t[32][33];
    const int tx = threadIdx.x, ty = threadIdx.y;          // 32 x 8
    const int bx = blockIdx.x, by = blockIdx.y;
    const int x = bx * 32 + tx;
#pragma unroll
    for (int i = 0; i < 4; i++) {
        const int y = by * 32 + ty + i * 8;
        t[ty + i * 8][tx] = W[(size_t)y * 512 + x];
    }
    __syncthreads();
    const int x2 = by * 32 + tx;                           // k
#pragma unroll
    for (int i = 0; i < 4; i++) {
        const int y2 = bx * 32 + ty + i * 8;               // n
        g_Wt[(size_t)y2 * 512 + x2] = tf32_rn(t[tx][ty + i * 8]);
    }
}

// ---------------------------------------------------------------------------
// Kernel 0b: row_ptr from sorted edge_dst. row_ptr[n] = first e with dst >= n.
// ---------------------------------------------------------------------------
__global__ void rowptr_kernel(const int* __restrict__ edge_dst) {
    const int e = blockIdx.x * blockDim.x + threadIdx.x;
    if (e > N_EDGES) return;
    const int d_prev = (e == 0)       ? -1      : edge_dst[e - 1];
    const int d_cur  = (e == N_EDGES) ? N_NODES : edge_dst[e];
    for (int n = d_prev + 1; n <= d_cur; n++) g_rowptr[n] = e;
}

// ---------------------------------------------------------------------------
// Kernel 1: dropout, JAX partitionable threefry-2x32-20; fp16 output.
// ---------------------------------------------------------------------------
__device__ __forceinline__ unsigned rotl32(unsigned x, int d) {
    return (x << d) | (x >> (32 - d));
}
__device__ __forceinline__ unsigned threefry_elem(unsigned i) {
    const unsigned ks0 = 0u, ks1 = 42u;
    const unsigned ks2 = ks0 ^ ks1 ^ 0x1BD11BDAu;
    unsigned x0 = 0u, x1 = i;
    x0 += ks0; x1 += ks1;
#define TF_ROUND(r) { x0 += x1; x1 = rotl32(x1, (r)); x1 ^= x0; }
    TF_ROUND(13) TF_ROUND(15) TF_ROUND(26) TF_ROUND(6)
    x0 += ks1; x1 += ks2 + 1u;
    TF_ROUND(17) TF_ROUND(29) TF_ROUND(16) TF_ROUND(24)
    x0 += ks2; x1 += ks0 + 2u;
    TF_ROUND(13) TF_ROUND(15) TF_ROUND(26) TF_ROUND(6)
    x0 += ks0; x1 += ks1 + 3u;
    TF_ROUND(17) TF_ROUND(29) TF_ROUND(16) TF_ROUND(24)
    x0 += ks1; x1 += ks2 + 4u;
    TF_ROUND(13) TF_ROUND(15) TF_ROUND(26) TF_ROUND(6)
    x0 += ks2; x1 += ks0 + 5u;
#undef TF_ROUND
    return x0 ^ x1;
}

__global__ void dropout_kernel(const float* __restrict__ x) {
    const unsigned base = (blockIdx.x * blockDim.x + threadIdx.x) * 4u;
    if (base >= (unsigned)N_ELEMS) return;
    const float4 v = __ldcs(reinterpret_cast<const float4*>(x + base));
    const float inv_keep = 1.0f / 0.9f;
    unsigned b0 = threefry_elem(base + 0u);
    unsigned b1 = threefry_elem(base + 1u);
    unsigned b2 = threefry_elem(base + 2u);
    unsigned b3 = threefry_elem(base + 3u);
    float u0 = __uint_as_float((b0 >> 9) | 0x3f800000u) - 1.0f;
    float u1 = __uint_as_float((b1 >> 9) | 0x3f800000u) - 1.0f;
    float u2 = __uint_as_float((b2 >> 9) | 0x3f800000u) - 1.0f;
    float u3 = __uint_as_float((b3 >> 9) | 0x3f800000u) - 1.0f;
    const float o0 = (u0 < 0.9f) ? v.x * inv_keep : 0.0f;
    const float o1 = (u1 < 0.9f) ? v.y * inv_keep : 0.0f;
    const float o2 = (u2 < 0.9f) ? v.z * inv_keep : 0.0f;
    const float o3 = (u3 < 0.9f) ? v.w * inv_keep : 0.0f;
    const __half2 h01 = __floats2half2_rn(o0, o1);
    const __half2 h23 = __floats2half2_rn(o2, o3);
    uint2 pack;
    pack.x = *reinterpret_cast<const uint32_t*>(&h01);
    pack.y = *reinterpret_cast<const uint32_t*>(&h23);
    *reinterpret_cast<uint2*>(g_xd_h + base) = pack;
}

// ---------------------------------------------------------------------------
// Kernel 2: segment-sum aggregation over fp16 xd (half the gather bytes;
// 51 MB working set is fully L2-resident). fp32 accumulate, tf32-round,
// streaming store. Thread f handles feats [4f, 4f+4) via one 8-byte load.
// ---------------------------------------------------------------------------
__global__ void agg_kernel(const float* __restrict__ edge_w,
                           const int*   __restrict__ edge_src) {
    const int node = blockIdx.x;
    const int start = g_rowptr[node];
    const int end   = g_rowptr[node + 1];

    const int f = threadIdx.x;  // 0..127
    float4 acc = make_float4(0.f, 0.f, 0.f, 0.f);

    int e = start;
#pragma unroll 1
    for (; e + 4 <= end; e += 4) {
        const float w0 = edge_w[e + 0], w1 = edge_w[e + 1];
        const float w2 = edge_w[e + 2], w3 = edge_w[e + 3];
        const int   s0 = edge_src[e + 0], s1 = edge_src[e + 1];
        const int   s2 = edge_src[e + 2], s3 = edge_src[e + 3];
        const uint2 r0 = reinterpret_cast<const uint2*>(g_xd_h + (size_t)s0 * FEATS)[f];
        const uint2 r1 = reinterpret_cast<const uint2*>(g_xd_h + (size_t)s1 * FEATS)[f];
        const uint2 r2 = reinterpret_cast<const uint2*>(g_xd_h + (size_t)s2 * FEATS)[f];
        const uint2 r3 = reinterpret_cast<const uint2*>(g_xd_h + (size_t)s3 * FEATS)[f];
#define ACC_EDGE(rr, ww) { \
        const float2 lo = __half22float2(*reinterpret_cast<const __half2*>(&(rr).x)); \
        const float2 hi = __half22float2(*reinterpret_cast<const __half2*>(&(rr).y)); \
        acc.x += (ww) * lo.x; acc.y += (ww) * lo.y; \
        acc.z += (ww) * hi.x; acc.w += (ww) * hi.y; }
        ACC_EDGE(r0, w0) ACC_EDGE(r1, w1) ACC_EDGE(r2, w2) ACC_EDGE(r3, w3)
    }
#pragma unroll 1
    for (; e < end; e++) {
        const float w = edge_w[e];
        const int   s = edge_src[e];
        const uint2 rr = reinterpret_cast<const uint2*>(g_xd_h + (size_t)s * FEATS)[f];
        ACC_EDGE(rr, w)
    }
#undef ACC_EDGE
    float4 r;
    r.x = tf32_rn(acc.x); r.y = tf32_rn(acc.y); r.z = tf32_rn(acc.z); r.w = tf32_rn(acc.w);
    __stcs(reinterpret_cast<float4*>(g_agg + (size_t)node * FEATS) + f, r);
}

// ---------------------------------------------------------------------------
// Kernel 3: mma.sync tf32 GEMM (unchanged from R7).
// 128x128 CTA tile, 4 warps, 64x64 warp tiles, BK=32, 2-stage cp.async.
// ---------------------------------------------------------------------------
#define BK 32
#define LDP 36                         // padded row stride (floats)
#define STAGE_F (128 * LDP)            // floats per stage per matrix
#define GEMM_SMEM_BYTES (4 * STAGE_F * 4)   // A0,A1,B0,B1

__global__ void __launch_bounds__(128, 2)
gemm_mma_kernel(const float* __restrict__ bias, float* __restrict__ out) {
    extern __shared__ float sm[];
    float* Asm = sm;                    // [2][128][LDP]
    float* Bsm = sm + 2 * STAGE_F;      // [2][128][LDP]

    const int tid   = threadIdx.x;
    const int wid   = tid >> 5;
    const int lane  = tid & 31;
    const int warpM = wid & 1;          // 0..1 -> M offset 0/64
    const int warpN = wid >> 1;         // 0..1 -> N offset 0/64
    const int m0 = blockIdx.y * 128;
    const int n0 = blockIdx.x * 128;

    const uint32_t aBase = smem_u32(Asm);
    const uint32_t bBase = smem_u32(Bsm);
    const uint32_t stageBytes = STAGE_F * 4;

    float acc[4][8][4];
#pragma unroll
    for (int i = 0; i < 4; i++)
#pragma unroll
        for (int j = 0; j < 8; j++)
#pragma unroll
            for (int r = 0; r < 4; r++) acc[i][j][r] = 0.f;

    auto load_tile = [&](int s, int k0) {
#pragma unroll
        for (int it = 0; it < 8; it++) {
            const int idx = it * 128 + tid;            // 0..1023
            const int row = idx >> 3, seg = idx & 7;
            cp_async16(aBase + s * stageBytes + (row * LDP + seg * 4) * 4,
                       &g_agg[(size_t)(m0 + row) * 512 + k0 + seg * 4]);
        }
#pragma unroll
        for (int it = 0; it < 8; it++) {
            const int idx = it * 128 + tid;
            const int row = idx >> 3, seg = idx & 7;
            cp_async16(bBase + s * stageBytes + (row * LDP + seg * 4) * 4,
                       &g_Wt[(size_t)(n0 + row) * 512 + k0 + seg * 4]);
        }
        cp_commit();
    };

    load_tile(0, 0);

    const int qrow = lane >> 2;   // 0..7
    const int qcol = lane & 3;    // 0..3

    for (int c = 0; c < 16; c++) {
        const int s = c & 1;
        cp_wait<0>();
        __syncthreads();
        if (c + 1 < 16) load_tile(s ^ 1, (c + 1) * BK);   // overlaps mma below

        const float* As = Asm + s * STAGE_F;
        const float* Bs = Bsm + s * STAGE_F;
#pragma unroll
        for (int kk = 0; kk < 4; kk++) {
            const int kb = kk * 8;
            uint32_t af[4][4];
#pragma unroll
            for (int mt = 0; mt < 4; mt++) {
                const int r0 = warpM * 64 + mt * 16 + qrow;
                af[mt][0] = __float_as_uint(As[r0 * LDP + kb + qcol]);
                af[mt][1] = __float_as_uint(As[(r0 + 8) * LDP + kb + qcol]);
                af[mt][2] = __float_as_uint(As[r0 * LDP + kb + 4 + qcol]);
                af[mt][3] = __float_as_uint(As[(r0 + 8) * LDP + kb + 4 + qcol]);
            }
            uint32_t bf[8][2];
#pragma unroll
            for (int nt = 0; nt < 8; nt++) {
                const int rn = warpN * 64 + nt * 8 + qrow;
                bf[nt][0] = __float_as_uint(Bs[rn * LDP + kb + qcol]);
                bf[nt][1] = __float_as_uint(Bs[rn * LDP + kb + 4 + qcol]);
            }
#pragma unroll
            for (int mt = 0; mt < 4; mt++)
#pragma unroll
                for (int nt = 0; nt < 8; nt++)
                    mma_tf32(acc[mt][nt], af[mt], bf[nt]);
        }
    }

    // epilogue: bias + relu, streaming stores
#pragma unroll
    for (int mt = 0; mt < 4; mt++) {
        const int row0 = m0 + warpM * 64 + mt * 16 + qrow;
        const int row1 = row0 + 8;
#pragma unroll
        for (int nt = 0; nt < 8; nt++) {
            const int col = n0 + warpN * 64 + nt * 8 + 2 * qcol;
            const float b0 = __ldg(bias + col);
            const float b1 = __ldg(bias + col + 1);
            if (row0 < N_NODES) {
                float2 o;
                o.x = fmaxf(acc[mt][nt][0] + b0, 0.f);
                o.y = fmaxf(acc[mt][nt][1] + b1, 0.f);
                __stcs(reinterpret_cast<float2*>(out + (size_t)row0 * 512 + col), o);
            }
            if (row1 < N_NODES) {
                float2 o;
                o.x = fmaxf(acc[mt][nt][2] + b0, 0.f);
                o.y = fmaxf(acc[mt][nt][3] + b1, 0.f);
                __stcs(reinterpret_cast<float2*>(out + (size_t)row1 * 512 + col), o);
            }
        }
    }
}

// ---------------------------------------------------------------------------
// Launch
// ---------------------------------------------------------------------------
extern "C" void kernel_launch(void* const* d_in, const int* in_sizes, int n_in,
                              void* d_out, int out_size) {
    const float* x        = (const float*)d_in[0];
    const float* edge_w   = (const float*)d_in[1];
    const float* W        = (const float*)d_in[2];
    const float* b        = (const float*)d_in[3];
    const int*   edge_src = (const int*)  d_in[4];
    const int*   edge_dst = (const int*)  d_in[5];
    float* out = (float*)d_out;

    cudaFuncSetAttribute(gemm_mma_kernel,
                         cudaFuncAttributeMaxDynamicSharedMemorySize, GEMM_SMEM_BYTES);

    transpose_W_kernel<<<dim3(16, 16), dim3(32, 8)>>>(W);
    rowptr_kernel<<<(N_EDGES + 256) / 256, 256>>>(edge_dst);
    dropout_kernel<<<(N_ELEMS / 4 + 255) / 256, 256>>>(x);
    agg_kernel<<<N_NODES, 128>>>(edge_w, edge_src);
    gemm_mma_kernel<<<dim3(4, M_TILES), 128, GEMM_SMEM_BYTES>>>(b, out);
}

// round 9
// speedup vs baseline: 1.6583x; 1.3188x over previous
#include <cuda_runtime.h>
#include <cuda_fp16.h>
#include <cstdint>

#define N_NODES 50000
#define N_EDGES 800000
#define FEATS   512
#define N_ELEMS (N_NODES * FEATS)
#define M_TILES 391                 // ceil(50000/128)
#define PAD_ROWS (M_TILES * 128)    // 50048

// Scratch (device globals). Zero-initialized; pad rows of g_agg_h stay zero.
__device__ __half g_xd_h [(size_t)N_NODES * FEATS];   // fp16 dropout output
__device__ __half g_agg_h[(size_t)PAD_ROWS * FEATS];  // fp16 agg output
__device__ __half g_Wt_h [(size_t)FEATS * FEATS];     // W^T fp16: Wt[n][k]
__device__ int    g_rowptr[N_NODES + 1];

// ---------------------------------------------------------------------------
// helpers
// ---------------------------------------------------------------------------
__device__ __forceinline__ uint32_t smem_u32(const void* p) {
    uint32_t a;
    asm("{ .reg .u64 t; cvta.to.shared.u64 t, %1; cvt.u32.u64 %0, t; }" : "=r"(a) : "l"(p));
    return a;
}
__device__ __forceinline__ void cp_async16(uint32_t dst, const void* src) {
    asm volatile("cp.async.cg.shared.global [%0], [%1], 16;" :: "r"(dst), "l"(src));
}
__device__ __forceinline__ void cp_commit() {
    asm volatile("cp.async.commit_group;" ::: "memory");
}
template <int N>
__device__ __forceinline__ void cp_wait() {
    asm volatile("cp.async.wait_group %0;" :: "n"(N) : "memory");
}
// D(16x8 f32) += A(16x16 f16, row) * B(16x8 f16, col)
__device__ __forceinline__ void mma_f16(float* c, const uint32_t* a, const uint32_t* b) {
    asm volatile(
        "mma.sync.aligned.m16n8k16.row.col.f32.f16.f16.f32 "
        "{%0,%1,%2,%3}, {%4,%5,%6,%7}, {%8,%9}, {%0,%1,%2,%3};"
        : "+f"(c[0]), "+f"(c[1]), "+f"(c[2]), "+f"(c[3])
        : "r"(a[0]), "r"(a[1]), "r"(a[2]), "r"(a[3]), "r"(b[0]), "r"(b[1]));
}

// ---------------------------------------------------------------------------
// Kernel 0a: Wt[n][k] = (fp16) W[k][n]
// ---------------------------------------------------------------------------
__global__ void transpose_W_kernel(const float* __restrict__ W) {
    __shared__ float t[32][33];
    const int tx = threadIdx.x, ty = threadIdx.y;          // 32 x 8
    const int bx = blockIdx.x, by = blockIdx.y;
    const int x = bx * 32 + tx;
#pragma unroll
    for (int i = 0; i < 4; i++) {
        const int y = by * 32 + ty + i * 8;
        t[ty + i * 8][tx] = W[(size_t)y * 512 + x];
    }
    __syncthreads();
    const int x2 = by * 32 + tx;                           // k
#pragma unroll
    for (int i = 0; i < 4; i++) {
        const int y2 = bx * 32 + ty + i * 8;               // n
        g_Wt_h[(size_t)y2 * 512 + x2] = __float2half_rn(t[tx][ty + i * 8]);
    }
}

// ---------------------------------------------------------------------------
// Kernel 0b: row_ptr from sorted edge_dst.
// ---------------------------------------------------------------------------
__global__ void rowptr_kernel(const int* __restrict__ edge_dst) {
    const int e = blockIdx.x * blockDim.x + threadIdx.x;
    if (e > N_EDGES) return;
    const int d_prev = (e == 0)       ? -1      : edge_dst[e - 1];
    const int d_cur  = (e == N_EDGES) ? N_NODES : edge_dst[e];
    for (int n = d_prev + 1; n <= d_cur; n++) g_rowptr[n] = e;
}

// ---------------------------------------------------------------------------
// Kernel 1: dropout, JAX partitionable threefry-2x32-20; fp16 output.
// ---------------------------------------------------------------------------
__device__ __forceinline__ unsigned rotl32(unsigned x, int d) {
    return (x << d) | (x >> (32 - d));
}
__device__ __forceinline__ unsigned threefry_elem(unsigned i) {
    const unsigned ks0 = 0u, ks1 = 42u;
    const unsigned ks2 = ks0 ^ ks1 ^ 0x1BD11BDAu;
    unsigned x0 = 0u, x1 = i;
    x0 += ks0; x1 += ks1;
#define TF_ROUND(r) { x0 += x1; x1 = rotl32(x1, (r)); x1 ^= x0; }
    TF_ROUND(13) TF_ROUND(15) TF_ROUND(26) TF_ROUND(6)
    x0 += ks1; x1 += ks2 + 1u;
    TF_ROUND(17) TF_ROUND(29) TF_ROUND(16) TF_ROUND(24)
    x0 += ks2; x1 += ks0 + 2u;
    TF_ROUND(13) TF_ROUND(15) TF_ROUND(26) TF_ROUND(6)
    x0 += ks0; x1 += ks1 + 3u;
    TF_ROUND(17) TF_ROUND(29) TF_ROUND(16) TF_ROUND(24)
    x0 += ks1; x1 += ks2 + 4u;
    TF_ROUND(13) TF_ROUND(15) TF_ROUND(26) TF_ROUND(6)
    x0 += ks2; x1 += ks0 + 5u;
#undef TF_ROUND
    return x0 ^ x1;
}

__global__ void dropout_kernel(const float* __restrict__ x) {
    const unsigned base = (blockIdx.x * blockDim.x + threadIdx.x) * 4u;
    if (base >= (unsigned)N_ELEMS) return;
    const float4 v = __ldcs(reinterpret_cast<const float4*>(x + base));
    const float inv_keep = 1.0f / 0.9f;
    unsigned b0 = threefry_elem(base + 0u);
    unsigned b1 = threefry_elem(base + 1u);
    unsigned b2 = threefry_elem(base + 2u);
    unsigned b3 = threefry_elem(base + 3u);
    float u0 = __uint_as_float((b0 >> 9) | 0x3f800000u) - 1.0f;
    float u1 = __uint_as_float((b1 >> 9) | 0x3f800000u) - 1.0f;
    float u2 = __uint_as_float((b2 >> 9) | 0x3f800000u) - 1.0f;
    float u3 = __uint_as_float((b3 >> 9) | 0x3f800000u) - 1.0f;
    const float o0 = (u0 < 0.9f) ? v.x * inv_keep : 0.0f;
    const float o1 = (u1 < 0.9f) ? v.y * inv_keep : 0.0f;
    const float o2 = (u2 < 0.9f) ? v.z * inv_keep : 0.0f;
    const float o3 = (u3 < 0.9f) ? v.w * inv_keep : 0.0f;
    const __half2 h01 = __floats2half2_rn(o0, o1);
    const __half2 h23 = __floats2half2_rn(o2, o3);
    uint2 pack;
    pack.x = *reinterpret_cast<const uint32_t*>(&h01);
    pack.y = *reinterpret_cast<const uint32_t*>(&h23);
    *reinterpret_cast<uint2*>(g_xd_h + base) = pack;
}

// ---------------------------------------------------------------------------
// Kernel 2: segment-sum aggregation over fp16 xd; fp32 accumulate; fp16 out.
// ---------------------------------------------------------------------------
__global__ void agg_kernel(const float* __restrict__ edge_w,
                           const int*   __restrict__ edge_src) {
    const int node = blockIdx.x;
    const int start = g_rowptr[node];
    const int end   = g_rowptr[node + 1];

    const int f = threadIdx.x;  // 0..127, owns feats [4f, 4f+4)
    float4 acc = make_float4(0.f, 0.f, 0.f, 0.f);

    int e = start;
#pragma unroll 1
    for (; e + 4 <= end; e += 4) {
        const float w0 = edge_w[e + 0], w1 = edge_w[e + 1];
        const float w2 = edge_w[e + 2], w3 = edge_w[e + 3];
        const int   s0 = edge_src[e + 0], s1 = edge_src[e + 1];
        const int   s2 = edge_src[e + 2], s3 = edge_src[e + 3];
        const uint2 r0 = reinterpret_cast<const uint2*>(g_xd_h + (size_t)s0 * FEATS)[f];
        const uint2 r1 = reinterpret_cast<const uint2*>(g_xd_h + (size_t)s1 * FEATS)[f];
        const uint2 r2 = reinterpret_cast<const uint2*>(g_xd_h + (size_t)s2 * FEATS)[f];
        const uint2 r3 = reinterpret_cast<const uint2*>(g_xd_h + (size_t)s3 * FEATS)[f];
#define ACC_EDGE(rr, ww) { \
        const float2 lo = __half22float2(*reinterpret_cast<const __half2*>(&(rr).x)); \
        const float2 hi = __half22float2(*reinterpret_cast<const __half2*>(&(rr).y)); \
        acc.x += (ww) * lo.x; acc.y += (ww) * lo.y; \
        acc.z += (ww) * hi.x; acc.w += (ww) * hi.y; }
        ACC_EDGE(r0, w0) ACC_EDGE(r1, w1) ACC_EDGE(r2, w2) ACC_EDGE(r3, w3)
    }
#pragma unroll 1
    for (; e < end; e++) {
        const float w = edge_w[e];
        const int   s = edge_src[e];
        const uint2 rr = reinterpret_cast<const uint2*>(g_xd_h + (size_t)s * FEATS)[f];
        ACC_EDGE(rr, w)
    }
#undef ACC_EDGE
    const __half2 h01 = __floats2half2_rn(acc.x, acc.y);
    const __half2 h23 = __floats2half2_rn(acc.z, acc.w);
    uint2 pack;
    pack.x = *reinterpret_cast<const uint32_t*>(&h01);
    pack.y = *reinterpret_cast<const uint32_t*>(&h23);
    __stcs(reinterpret_cast<uint2*>(g_agg_h + (size_t)node * FEATS) + f, pack);
}

// ---------------------------------------------------------------------------
// Kernel 3: fp16 mma.sync m16n8k16 GEMM, fp32 accum. out = relu(agg @ W + b).
// 128x128 CTA tile, 4 warps (64x64 warp tiles), BK=64 halves, 2-stage
// cp.async. Smem rows 144 B (stride 36 banks -> row r uses banks 4r..4r+3,
// conflict-free fragment LDS.b32).
// ---------------------------------------------------------------------------
#define BKH 64                          // halves per K chunk
#define LDH 72                          // padded halves per row (144 B)
#define STAGE_H (128 * LDH)             // halves per stage per matrix
#define GEMM_SMEM_BYTES (4 * STAGE_H * 2)   // A0,A1,B0,B1 = 73728 B

__global__ void __launch_bounds__(128, 2)
gemm_mma_kernel(const float* __restrict__ bias, float* __restrict__ out) {
    extern __shared__ __half smh[];
    __half* Asm = smh;                  // [2][128][LDH]
    __half* Bsm = smh + 2 * STAGE_H;    // [2][128][LDH]

    const int tid   = threadIdx.x;
    const int wid   = tid >> 5;
    const int lane  = tid & 31;
    const int warpM = wid & 1;          // M offset 0/64
    const int warpN = wid >> 1;         // N offset 0/64
    const int m0 = blockIdx.y * 128;
    const int n0 = blockIdx.x * 128;

    const uint32_t aBase = smem_u32(Asm);
    const uint32_t bBase = smem_u32(Bsm);
    const uint32_t stageBytes = STAGE_H * 2;

    float acc[4][8][4];
#pragma unroll
    for (int i = 0; i < 4; i++)
#pragma unroll
        for (int j = 0; j < 8; j++)
#pragma unroll
            for (int r = 0; r < 4; r++) acc[i][j][r] = 0.f;

    // one K chunk: 128 rows x 64 halves (128 B) per matrix
    auto load_tile = [&](int s, int k0) {
#pragma unroll
        for (int it = 0; it < 8; it++) {
            const int idx = it * 128 + tid;            // 0..1023
            const int row = idx >> 3, seg = idx & 7;   // 8 x 16B per row
            cp_async16(aBase + s * stageBytes + row * 144 + seg * 16,
                       g_agg_h + (size_t)(m0 + row) * 512 + k0 + seg * 8);
        }
#pragma unroll
        for (int it = 0; it < 8; it++) {
            const int idx = it * 128 + tid;
            const int row = idx >> 3, seg = idx & 7;
            cp_async16(bBase + s * stageBytes + row * 144 + seg * 16,
                       g_Wt_h + (size_t)(n0 + row) * 512 + k0 + seg * 8);
        }
        cp_commit();
    };

    load_tile(0, 0);

    const int qrow = lane >> 2;   // fragment group id (0..7)
    const int qcol = lane & 3;    // thread-in-group (0..3)

    for (int c = 0; c < 8; c++) {
        const int s = c & 1;
        cp_wait<0>();
        __syncthreads();
        if (c + 1 < 8) load_tile(s ^ 1, (c + 1) * BKH);   // overlaps mma below

        const __half* As = Asm + s * STAGE_H;
        const __half* Bs = Bsm + s * STAGE_H;
#pragma unroll
        for (int kk = 0; kk < 4; kk++) {
            const int kb = kk * 16;                       // halves
            uint32_t af[4][4];
#pragma unroll
            for (int mt = 0; mt < 4; mt++) {
                const int r0 = warpM * 64 + mt * 16 + qrow;
                af[mt][0] = *reinterpret_cast<const uint32_t*>(&As[r0 * LDH + kb + 2 * qcol]);
                af[mt][1] = *reinterpret_cast<const uint32_t*>(&As[(r0 + 8) * LDH + kb + 2 * qcol]);
                af[mt][2] = *reinterpret_cast<const uint32_t*>(&As[r0 * LDH + kb + 8 + 2 * qcol]);
                af[mt][3] = *reinterpret_cast<const uint32_t*>(&As[(r0 + 8) * LDH + kb + 8 + 2 * qcol]);
            }
            uint32_t bf[8][2];
#pragma unroll
            for (int nt = 0; nt < 8; nt++) {
                const int rn = warpN * 64 + nt * 8 + qrow;
                bf[nt][0] = *reinterpret_cast<const uint32_t*>(&Bs[rn * LDH + kb + 2 * qcol]);
                bf[nt][1] = *reinterpret_cast<const uint32_t*>(&Bs[rn * LDH + kb + 8 + 2 * qcol]);
            }
#pragma unroll
            for (int mt = 0; mt < 4; mt++)
#pragma unroll
                for (int nt = 0; nt < 8; nt++)
                    mma_f16(acc[mt][nt], af[mt], bf[nt]);
        }
    }

    // epilogue: bias + relu, streaming stores
#pragma unroll
    for (int mt = 0; mt < 4; mt++) {
        const int row0 = m0 + warpM * 64 + mt * 16 + qrow;
        const int row1 = row0 + 8;
#pragma unroll
        for (int nt = 0; nt < 8; nt++) {
            const int col = n0 + warpN * 64 + nt * 8 + 2 * qcol;
            const float b0 = __ldg(bias + col);
            const float b1 = __ldg(bias + col + 1);
            if (row0 < N_NODES) {
                float2 o;
                o.x = fmaxf(acc[mt][nt][0] + b0, 0.f);
                o.y = fmaxf(acc[mt][nt][1] + b1, 0.f);
                __stcs(reinterpret_cast<float2*>(out + (size_t)row0 * 512 + col), o);
            }
            if (row1 < N_NODES) {
                float2 o;
                o.x = fmaxf(acc[mt][nt][2] + b0, 0.f);
                o.y = fmaxf(acc[mt][nt][3] + b1, 0.f);
                __stcs(reinterpret_cast<float2*>(out + (size_t)row1 * 512 + col), o);
            }
        }
    }
}

// ---------------------------------------------------------------------------
// Launch
// ---------------------------------------------------------------------------
extern "C" void kernel_launch(void* const* d_in, const int* in_sizes, int n_in,
                              void* d_out, int out_size) {
    const float* x        = (const float*)d_in[0];
    const float* edge_w   = (const float*)d_in[1];
    const float* W        = (const float*)d_in[2];
    const float* b        = (const float*)d_in[3];
    const int*   edge_src = (const int*)  d_in[4];
    const int*   edge_dst = (const int*)  d_in[5];
    float* out = (float*)d_out;

    cudaFuncSetAttribute(gemm_mma_kernel,
                         cudaFuncAttributeMaxDynamicSharedMemorySize, GEMM_SMEM_BYTES);

    transpose_W_kernel<<<dim3(16, 16), dim3(32, 8)>>>(W);
    rowptr_kernel<<<(N_EDGES + 256) / 256, 256>>>(edge_dst);
    dropout_kernel<<<(N_ELEMS / 4 + 255) / 256, 256>>>(x);
    agg_kernel<<<N_NODES, 128>>>(edge_w, edge_src);
    gemm_mma_kernel<<<dim3(4, M_TILES), 128, GEMM_SMEM_BYTES>>>(b, out);
}

// round 10
// speedup vs baseline: 1.6757x; 1.0105x over previous
#include <cuda_runtime.h>
#include <cuda_fp16.h>
#include <cstdint>

#define N_NODES 50000
#define N_EDGES 800000
#define FEATS   512
#define N_ELEMS (N_NODES * FEATS)
#define M_TILES 391                 // ceil(50000/128)
#define PAD_ROWS (M_TILES * 128)    // 50048

// Scratch (device globals). Zero-initialized; pad rows of g_agg_h stay zero.
__device__ __half g_xd_h [(size_t)N_NODES * FEATS];   // fp16 dropout output
__device__ __half g_agg_h[(size_t)PAD_ROWS * FEATS];  // fp16 agg output
__device__ __half g_Wt_h [(size_t)FEATS * FEATS];     // W^T fp16: Wt[n][k]
__device__ int    g_rowptr[N_NODES + 1];

// ---------------------------------------------------------------------------
// helpers
// ---------------------------------------------------------------------------
__device__ __forceinline__ uint32_t smem_u32(const void* p) {
    uint32_t a;
    asm("{ .reg .u64 t; cvta.to.shared.u64 t, %1; cvt.u32.u64 %0, t; }" : "=r"(a) : "l"(p));
    return a;
}
__device__ __forceinline__ void cp_async16(uint32_t dst, const void* src) {
    asm volatile("cp.async.cg.shared.global [%0], [%1], 16;" :: "r"(dst), "l"(src));
}
__device__ __forceinline__ void cp_commit() {
    asm volatile("cp.async.commit_group;" ::: "memory");
}
template <int N>
__device__ __forceinline__ void cp_wait() {
    asm volatile("cp.async.wait_group %0;" :: "n"(N) : "memory");
}
// D(16x8 f32) += A(16x16 f16, row) * B(16x8 f16, col)
__device__ __forceinline__ void mma_f16(float* c, const uint32_t* a, const uint32_t* b) {
    asm volatile(
        "mma.sync.aligned.m16n8k16.row.col.f32.f16.f16.f32 "
        "{%0,%1,%2,%3}, {%4,%5,%6,%7}, {%8,%9}, {%0,%1,%2,%3};"
        : "+f"(c[0]), "+f"(c[1]), "+f"(c[2]), "+f"(c[3])
        : "r"(a[0]), "r"(a[1]), "r"(a[2]), "r"(a[3]), "r"(b[0]), "r"(b[1]));
}
__device__ __forceinline__ void ldsm_x4(uint32_t& r0, uint32_t& r1, uint32_t& r2,
                                        uint32_t& r3, uint32_t addr) {
    asm volatile("ldmatrix.sync.aligned.m8n8.x4.shared.b16 {%0,%1,%2,%3}, [%4];"
                 : "=r"(r0), "=r"(r1), "=r"(r2), "=r"(r3) : "r"(addr));
}

// ---------------------------------------------------------------------------
// Kernel 0a: Wt[n][k] = (fp16) W[k][n]
// ---------------------------------------------------------------------------
__global__ void transpose_W_kernel(const float* __restrict__ W) {
    __shared__ float t[32][33];
    const int tx = threadIdx.x, ty = threadIdx.y;          // 32 x 8
    const int bx = blockIdx.x, by = blockIdx.y;
    const int x = bx * 32 + tx;
#pragma unroll
    for (int i = 0; i < 4; i++) {
        const int y = by * 32 + ty + i * 8;
        t[ty + i * 8][tx] = W[(size_t)y * 512 + x];
    }
    __syncthreads();
    const int x2 = by * 32 + tx;                           // k
#pragma unroll
    for (int i = 0; i < 4; i++) {
        const int y2 = bx * 32 + ty + i * 8;               // n
        g_Wt_h[(size_t)y2 * 512 + x2] = __float2half_rn(t[tx][ty + i * 8]);
    }
}

// ---------------------------------------------------------------------------
// Kernel 0b: row_ptr from sorted edge_dst.
// ---------------------------------------------------------------------------
__global__ void rowptr_kernel(const int* __restrict__ edge_dst) {
    const int e = blockIdx.x * blockDim.x + threadIdx.x;
    if (e > N_EDGES) return;
    const int d_prev = (e == 0)       ? -1      : edge_dst[e - 1];
    const int d_cur  = (e == N_EDGES) ? N_NODES : edge_dst[e];
    for (int n = d_prev + 1; n <= d_cur; n++) g_rowptr[n] = e;
}

// ---------------------------------------------------------------------------
// Kernel 1: dropout, JAX partitionable threefry-2x32-20; fp16 output.
// keep <=> bits < 0xE6666600 (== 7549747*512; exact integer form of u < 0.9f).
// ---------------------------------------------------------------------------
__device__ __forceinline__ unsigned rotl32(unsigned x, int d) {
    return (x << d) | (x >> (32 - d));
}
__device__ __forceinline__ unsigned threefry_elem(unsigned i) {
    const unsigned ks0 = 0u, ks1 = 42u;
    const unsigned ks2 = ks0 ^ ks1 ^ 0x1BD11BDAu;
    unsigned x0 = 0u, x1 = i;
    x0 += ks0; x1 += ks1;
#define TF_ROUND(r) { x0 += x1; x1 = rotl32(x1, (r)); x1 ^= x0; }
    TF_ROUND(13) TF_ROUND(15) TF_ROUND(26) TF_ROUND(6)
    x0 += ks1; x1 += ks2 + 1u;
    TF_ROUND(17) TF_ROUND(29) TF_ROUND(16) TF_ROUND(24)
    x0 += ks2; x1 += ks0 + 2u;
    TF_ROUND(13) TF_ROUND(15) TF_ROUND(26) TF_ROUND(6)
    x0 += ks0; x1 += ks1 + 3u;
    TF_ROUND(17) TF_ROUND(29) TF_ROUND(16) TF_ROUND(24)
    x0 += ks1; x1 += ks2 + 4u;
    TF_ROUND(13) TF_ROUND(15) TF_ROUND(26) TF_ROUND(6)
    x0 += ks2; x1 += ks0 + 5u;
#undef TF_ROUND
    return x0 ^ x1;
}

__global__ void dropout_kernel(const float* __restrict__ x) {
    const unsigned base = (blockIdx.x * blockDim.x + threadIdx.x) * 4u;
    if (base >= (unsigned)N_ELEMS) return;
    const float4 v = __ldcs(reinterpret_cast<const float4*>(x + base));
    const float inv_keep = 1.0f / 0.9f;
    const unsigned b0 = threefry_elem(base + 0u);
    const unsigned b1 = threefry_elem(base + 1u);
    const unsigned b2 = threefry_elem(base + 2u);
    const unsigned b3 = threefry_elem(base + 3u);
    const unsigned THR = 0xE6666600u;   // 7549747 << 9
    const float o0 = (b0 < THR) ? v.x * inv_keep : 0.0f;
    const float o1 = (b1 < THR) ? v.y * inv_keep : 0.0f;
    const float o2 = (b2 < THR) ? v.z * inv_keep : 0.0f;
    const float o3 = (b3 < THR) ? v.w * inv_keep : 0.0f;
    const __half2 h01 = __floats2half2_rn(o0, o1);
    const __half2 h23 = __floats2half2_rn(o2, o3);
    uint2 pack;
    pack.x = *reinterpret_cast<const uint32_t*>(&h01);
    pack.y = *reinterpret_cast<const uint32_t*>(&h23);
    *reinterpret_cast<uint2*>(g_xd_h + base) = pack;
}

// ---------------------------------------------------------------------------
// Kernel 2: segment-sum aggregation over fp16 xd; fp32 accumulate; fp16 out.
// (unchanged from R9 — issue-bound near its floor for this structure)
// ---------------------------------------------------------------------------
__global__ void agg_kernel(const float* __restrict__ edge_w,
                           const int*   __restrict__ edge_src) {
    const int node = blockIdx.x;
    const int start = g_rowptr[node];
    const int end   = g_rowptr[node + 1];

    const int f = threadIdx.x;  // 0..127, owns feats [4f, 4f+4)
    float4 acc = make_float4(0.f, 0.f, 0.f, 0.f);

    int e = start;
#pragma unroll 1
    for (; e + 4 <= end; e += 4) {
        const float w0 = edge_w[e + 0], w1 = edge_w[e + 1];
        const float w2 = edge_w[e + 2], w3 = edge_w[e + 3];
        const int   s0 = edge_src[e + 0], s1 = edge_src[e + 1];
        const int   s2 = edge_src[e + 2], s3 = edge_src[e + 3];
        const uint2 r0 = reinterpret_cast<const uint2*>(g_xd_h + (size_t)s0 * FEATS)[f];
        const uint2 r1 = reinterpret_cast<const uint2*>(g_xd_h + (size_t)s1 * FEATS)[f];
        const uint2 r2 = reinterpret_cast<const uint2*>(g_xd_h + (size_t)s2 * FEATS)[f];
        const uint2 r3 = reinterpret_cast<const uint2*>(g_xd_h + (size_t)s3 * FEATS)[f];
#define ACC_EDGE(rr, ww) { \
        const float2 lo = __half22float2(*reinterpret_cast<const __half2*>(&(rr).x)); \
        const float2 hi = __half22float2(*reinterpret_cast<const __half2*>(&(rr).y)); \
        acc.x += (ww) * lo.x; acc.y += (ww) * lo.y; \
        acc.z += (ww) * hi.x; acc.w += (ww) * hi.y; }
        ACC_EDGE(r0, w0) ACC_EDGE(r1, w1) ACC_EDGE(r2, w2) ACC_EDGE(r3, w3)
    }
#pragma unroll 1
    for (; e < end; e++) {
        const float w = edge_w[e];
        const int   s = edge_src[e];
        const uint2 rr = reinterpret_cast<const uint2*>(g_xd_h + (size_t)s * FEATS)[f];
        ACC_EDGE(rr, w)
    }
#undef ACC_EDGE
    const __half2 h01 = __floats2half2_rn(acc.x, acc.y);
    const __half2 h23 = __floats2half2_rn(acc.z, acc.w);
    uint2 pack;
    pack.x = *reinterpret_cast<const uint32_t*>(&h01);
    pack.y = *reinterpret_cast<const uint32_t*>(&h23);
    __stcs(reinterpret_cast<uint2*>(g_agg_h + (size_t)node * FEATS) + f, pack);
}

// ---------------------------------------------------------------------------
// Kernel 3: fp16 mma.sync m16n8k16 GEMM, fp32 accum, fragment loads via
// ldmatrix.x4 (8 shared-load inst per kk-step per warp instead of 32).
// 128x128 CTA tile, 4 warps (64x64 warp tiles), BK=64 halves, 2-stage
// cp.async. Smem rows 144 B -> ldmatrix 8-row phases cover all 32 banks.
// ---------------------------------------------------------------------------
#define BKH 64                          // halves per K chunk
#define LDH 72                          // padded halves per row (144 B)
#define STAGE_H (128 * LDH)             // halves per stage per matrix
#define GEMM_SMEM_BYTES (4 * STAGE_H * 2)   // A0,A1,B0,B1 = 73728 B

__global__ void __launch_bounds__(128, 2)
gemm_mma_kernel(const float* __restrict__ bias, float* __restrict__ out) {
    extern __shared__ __half smh[];
    __half* Asm = smh;                  // [2][128][LDH]
    __half* Bsm = smh + 2 * STAGE_H;    // [2][128][LDH]

    const int tid   = threadIdx.x;
    const int wid   = tid >> 5;
    const int lane  = tid & 31;
    const int warpM = wid & 1;          // M offset 0/64
    const int warpN = wid >> 1;         // N offset 0/64
    const int m0 = blockIdx.y * 128;
    const int n0 = blockIdx.x * 128;

    const uint32_t aBase = smem_u32(Asm);
    const uint32_t bBase = smem_u32(Bsm);
    const uint32_t stageBytes = STAGE_H * 2;

    // ldmatrix lane->address templates (bytes, within a stage)
    // A x4: m0=rows(lane&15)+R, k0-7 | m1 same +8rows handled by lane&15 span |
    //       lanes 16-31 -> k-half 8..15
    const int rA   = warpM * 64 + (lane & 15);
    const int kAh  = (lane & 16) ? 8 : 0;              // halves
    const uint32_t aLane = (uint32_t)(rA * LDH + kAh) * 2;
    // B x4: two 8-row n-tiles per op; lanes 0-15 tile ntp*16+0..7 (lane&8 -> k-half),
    //       lanes 16-31 -> +8 n rows
    const int rB   = warpN * 64 + (lane & 7) + ((lane & 16) >> 1);
    const int kBh  = (lane & 8) ? 8 : 0;
    const uint32_t bLane = (uint32_t)(rB * LDH + kBh) * 2;

    float acc[4][8][4];
#pragma unroll
    for (int i = 0; i < 4; i++)
#pragma unroll
        for (int j = 0; j < 8; j++)
#pragma unroll
            for (int r = 0; r < 4; r++) acc[i][j][r] = 0.f;

    // one K chunk: 128 rows x 64 halves (128 B) per matrix
    auto load_tile = [&](int s, int k0) {
#pragma unroll
        for (int it = 0; it < 8; it++) {
            const int idx = it * 128 + tid;            // 0..1023
            const int row = idx >> 3, seg = idx & 7;   // 8 x 16B per row
            cp_async16(aBase + s * stageBytes + row * 144 + seg * 16,
                       g_agg_h + (size_t)(m0 + row) * 512 + k0 + seg * 8);
        }
#pragma unroll
        for (int it = 0; it < 8; it++) {
            const int idx = it * 128 + tid;
            const int row = idx >> 3, seg = idx & 7;
            cp_async16(bBase + s * stageBytes + row * 144 + seg * 16,
                       g_Wt_h + (size_t)(n0 + row) * 512 + k0 + seg * 8);
        }
        cp_commit();
    };

    load_tile(0, 0);

    for (int c = 0; c < 8; c++) {
        const int s = c & 1;
        cp_wait<0>();
        __syncthreads();
        if (c + 1 < 8) load_tile(s ^ 1, (c + 1) * BKH);   // overlaps mma below

        const uint32_t aStage = aBase + s * stageBytes + aLane;
        const uint32_t bStage = bBase + s * stageBytes + bLane;
#pragma unroll
        for (int kk = 0; kk < 4; kk++) {
            const uint32_t kOff = kk * 32;                // 16 halves = 32 B
            uint32_t af[4][4];
#pragma unroll
            for (int mt = 0; mt < 4; mt++)
                ldsm_x4(af[mt][0], af[mt][1], af[mt][2], af[mt][3],
                        aStage + (uint32_t)(mt * 16 * LDH) * 2 + kOff);
            uint32_t bf[8][2];
#pragma unroll
            for (int ntp = 0; ntp < 4; ntp++)
                ldsm_x4(bf[2 * ntp][0], bf[2 * ntp][1],
                        bf[2 * ntp + 1][0], bf[2 * ntp + 1][1],
                        bStage + (uint32_t)(ntp * 16 * LDH) * 2 + kOff);
#pragma unroll
            for (int mt = 0; mt < 4; mt++)
#pragma unroll
                for (int nt = 0; nt < 8; nt++)
                    mma_f16(acc[mt][nt], af[mt], bf[nt]);
        }
    }

    const int qrow = lane >> 2;
    const int qcol = lane & 3;

    // epilogue: bias + relu, streaming stores
#pragma unroll
    for (int mt = 0; mt < 4; mt++) {
        const int row0 = m0 + warpM * 64 + mt * 16 + qrow;
        const int row1 = row0 + 8;
#pragma unroll
        for (int nt = 0; nt < 8; nt++) {
            const int col = n0 + warpN * 64 + nt * 8 + 2 * qcol;
            const float b0 = __ldg(bias + col);
            const float b1 = __ldg(bias + col + 1);
            if (row0 < N_NODES) {
                float2 o;
                o.x = fmaxf(acc[mt][nt][0] + b0, 0.f);
                o.y = fmaxf(acc[mt][nt][1] + b1, 0.f);
                __stcs(reinterpret_cast<float2*>(out + (size_t)row0 * 512 + col), o);
            }
            if (row1 < N_NODES) {
                float2 o;
                o.x = fmaxf(acc[mt][nt][2] + b0, 0.f);
                o.y = fmaxf(acc[mt][nt][3] + b1, 0.f);
                __stcs(reinterpret_cast<float2*>(out + (size_t)row1 * 512 + col), o);
            }
        }
    }
}

// ---------------------------------------------------------------------------
// Launch
// ---------------------------------------------------------------------------
extern "C" void kernel_launch(void* const* d_in, const int* in_sizes, int n_in,
                              void* d_out, int out_size) {
    const float* x        = (const float*)d_in[0];
    const float* edge_w   = (const float*)d_in[1];
    const float* W        = (const float*)d_in[2];
    const float* b        = (const float*)d_in[3];
    const int*   edge_src = (const int*)  d_in[4];
    const int*   edge_dst = (const int*)  d_in[5];
    float* out = (float*)d_out;

    cudaFuncSetAttribute(gemm_mma_kernel,
                         cudaFuncAttributeMaxDynamicSharedMemorySize, GEMM_SMEM_BYTES);

    transpose_W_kernel<<<dim3(16, 16), dim3(32, 8)>>>(W);
    rowptr_kernel<<<(N_EDGES + 256) / 256, 256>>>(edge_dst);
    dropout_kernel<<<(N_ELEMS / 4 + 255) / 256, 256>>>(x);
    agg_kernel<<<N_NODES, 128>>>(edge_w, edge_src);
    gemm_mma_kernel<<<dim3(4, M_TILES), 128, GEMM_SMEM_BYTES>>>(b, out);
}

// round 11
// speedup vs baseline: 1.7016x; 1.0155x over previous
#include <cuda_runtime.h>
#include <cuda_fp16.h>
#include <cstdint>

#define N_NODES 50000
#define N_EDGES 800000
#define FEATS   512
#define N_ELEMS (N_NODES * FEATS)
#define M_TILES 391                 // ceil(50000/128)
#define PAD_ROWS (M_TILES * 128)    // 50048

// Scratch (device globals). Zero-initialized; pad rows of g_agg_h stay zero.
__device__ __half g_xd_h [(size_t)N_NODES * FEATS];   // fp16 dropout output
__device__ __half g_agg_h[(size_t)PAD_ROWS * FEATS];  // fp16 agg output
__device__ __half g_Wt_h [(size_t)FEATS * FEATS];     // W^T fp16: Wt[n][k]
__device__ int    g_rowptr[N_NODES + 1];

// ---------------------------------------------------------------------------
// helpers
// ---------------------------------------------------------------------------
__device__ __forceinline__ uint32_t smem_u32(const void* p) {
    uint32_t a;
    asm("{ .reg .u64 t; cvta.to.shared.u64 t, %1; cvt.u32.u64 %0, t; }" : "=r"(a) : "l"(p));
    return a;
}
__device__ __forceinline__ void cp_async16(uint32_t dst, const void* src) {
    asm volatile("cp.async.cg.shared.global [%0], [%1], 16;" :: "r"(dst), "l"(src));
}
__device__ __forceinline__ void cp_commit() {
    asm volatile("cp.async.commit_group;" ::: "memory");
}
template <int N>
__device__ __forceinline__ void cp_wait() {
    asm volatile("cp.async.wait_group %0;" :: "n"(N) : "memory");
}
// D(16x8 f32) += A(16x16 f16, row) * B(16x8 f16, col)
__device__ __forceinline__ void mma_f16(float* c, const uint32_t* a, const uint32_t* b) {
    asm volatile(
        "mma.sync.aligned.m16n8k16.row.col.f32.f16.f16.f32 "
        "{%0,%1,%2,%3}, {%4,%5,%6,%7}, {%8,%9}, {%0,%1,%2,%3};"
        : "+f"(c[0]), "+f"(c[1]), "+f"(c[2]), "+f"(c[3])
        : "r"(a[0]), "r"(a[1]), "r"(a[2]), "r"(a[3]), "r"(b[0]), "r"(b[1]));
}
__device__ __forceinline__ void ldsm_x4(uint32_t& r0, uint32_t& r1, uint32_t& r2,
                                        uint32_t& r3, uint32_t addr) {
    asm volatile("ldmatrix.sync.aligned.m8n8.x4.shared.b16 {%0,%1,%2,%3}, [%4];"
                 : "=r"(r0), "=r"(r1), "=r"(r2), "=r"(r3) : "r"(addr));
}

// ---------------------------------------------------------------------------
// Kernel 0a: Wt[n][k] = (fp16) W[k][n]
// ---------------------------------------------------------------------------
__global__ void transpose_W_kernel(const float* __restrict__ W) {
    __shared__ float t[32][33];
    const int tx = threadIdx.x, ty = threadIdx.y;          // 32 x 8
    const int bx = blockIdx.x, by = blockIdx.y;
    const int x = bx * 32 + tx;
#pragma unroll
    for (int i = 0; i < 4; i++) {
        const int y = by * 32 + ty + i * 8;
        t[ty + i * 8][tx] = W[(size_t)y * 512 + x];
    }
    __syncthreads();
    const int x2 = by * 32 + tx;                           // k
#pragma unroll
    for (int i = 0; i < 4; i++) {
        const int y2 = bx * 32 + ty + i * 8;               // n
        g_Wt_h[(size_t)y2 * 512 + x2] = __float2half_rn(t[tx][ty + i * 8]);
    }
}

// ---------------------------------------------------------------------------
// Kernel 0b: row_ptr from sorted edge_dst.
// ---------------------------------------------------------------------------
__global__ void rowptr_kernel(const int* __restrict__ edge_dst) {
    const int e = blockIdx.x * blockDim.x + threadIdx.x;
    if (e > N_EDGES) return;
    const int d_prev = (e == 0)       ? -1      : edge_dst[e - 1];
    const int d_cur  = (e == N_EDGES) ? N_NODES : edge_dst[e];
    for (int n = d_prev + 1; n <= d_cur; n++) g_rowptr[n] = e;
}

// ---------------------------------------------------------------------------
// Kernel 1: dropout, JAX partitionable threefry-2x32-20; fp16 output.
// keep <=> bits < 0xE6666600 (== 7549747<<9; exact integer form of u < 0.9f).
// ---------------------------------------------------------------------------
__device__ __forceinline__ unsigned rotl32(unsigned x, int d) {
    return (x << d) | (x >> (32 - d));
}
__device__ __forceinline__ unsigned threefry_elem(unsigned i) {
    const unsigned ks0 = 0u, ks1 = 42u;
    const unsigned ks2 = ks0 ^ ks1 ^ 0x1BD11BDAu;
    unsigned x0 = 0u, x1 = i;
    x0 += ks0; x1 += ks1;
#define TF_ROUND(r) { x0 += x1; x1 = rotl32(x1, (r)); x1 ^= x0; }
    TF_ROUND(13) TF_ROUND(15) TF_ROUND(26) TF_ROUND(6)
    x0 += ks1; x1 += ks2 + 1u;
    TF_ROUND(17) TF_ROUND(29) TF_ROUND(16) TF_ROUND(24)
    x0 += ks2; x1 += ks0 + 2u;
    TF_ROUND(13) TF_ROUND(15) TF_ROUND(26) TF_ROUND(6)
    x0 += ks0; x1 += ks1 + 3u;
    TF_ROUND(17) TF_ROUND(29) TF_ROUND(16) TF_ROUND(24)
    x0 += ks1; x1 += ks2 + 4u;
    TF_ROUND(13) TF_ROUND(15) TF_ROUND(26) TF_ROUND(6)
    x0 += ks2; x1 += ks0 + 5u;
#undef TF_ROUND
    return x0 ^ x1;
}

__global__ void dropout_kernel(const float* __restrict__ x) {
    const unsigned base = (blockIdx.x * blockDim.x + threadIdx.x) * 4u;
    if (base >= (unsigned)N_ELEMS) return;
    const float4 v = __ldcs(reinterpret_cast<const float4*>(x + base));
    const float inv_keep = 1.0f / 0.9f;
    const unsigned b0 = threefry_elem(base + 0u);
    const unsigned b1 = threefry_elem(base + 1u);
    const unsigned b2 = threefry_elem(base + 2u);
    const unsigned b3 = threefry_elem(base + 3u);
    const unsigned THR = 0xE6666600u;
    const float o0 = (b0 < THR) ? v.x * inv_keep : 0.0f;
    const float o1 = (b1 < THR) ? v.y * inv_keep : 0.0f;
    const float o2 = (b2 < THR) ? v.z * inv_keep : 0.0f;
    const float o3 = (b3 < THR) ? v.w * inv_keep : 0.0f;
    const __half2 h01 = __floats2half2_rn(o0, o1);
    const __half2 h23 = __floats2half2_rn(o2, o3);
    uint2 pack;
    pack.x = *reinterpret_cast<const uint32_t*>(&h01);
    pack.y = *reinterpret_cast<const uint32_t*>(&h23);
    *reinterpret_cast<uint2*>(g_xd_h + base) = pack;
}

// ---------------------------------------------------------------------------
// Kernel 2: segment-sum aggregation over fp16 xd; fp32 accumulate; fp16 out.
// ---------------------------------------------------------------------------
__global__ void agg_kernel(const float* __restrict__ edge_w,
                           const int*   __restrict__ edge_src) {
    const int node = blockIdx.x;
    const int start = g_rowptr[node];
    const int end   = g_rowptr[node + 1];

    const int f = threadIdx.x;  // 0..127, owns feats [4f, 4f+4)
    float4 acc = make_float4(0.f, 0.f, 0.f, 0.f);

    int e = start;
#pragma unroll 1
    for (; e + 4 <= end; e += 4) {
        const float w0 = edge_w[e + 0], w1 = edge_w[e + 1];
        const float w2 = edge_w[e + 2], w3 = edge_w[e + 3];
        const int   s0 = edge_src[e + 0], s1 = edge_src[e + 1];
        const int   s2 = edge_src[e + 2], s3 = edge_src[e + 3];
        const uint2 r0 = reinterpret_cast<const uint2*>(g_xd_h + (size_t)s0 * FEATS)[f];
        const uint2 r1 = reinterpret_cast<const uint2*>(g_xd_h + (size_t)s1 * FEATS)[f];
        const uint2 r2 = reinterpret_cast<const uint2*>(g_xd_h + (size_t)s2 * FEATS)[f];
        const uint2 r3 = reinterpret_cast<const uint2*>(g_xd_h + (size_t)s3 * FEATS)[f];
#define ACC_EDGE(rr, ww) { \
        const float2 lo = __half22float2(*reinterpret_cast<const __half2*>(&(rr).x)); \
        const float2 hi = __half22float2(*reinterpret_cast<const __half2*>(&(rr).y)); \
        acc.x += (ww) * lo.x; acc.y += (ww) * lo.y; \
        acc.z += (ww) * hi.x; acc.w += (ww) * hi.y; }
        ACC_EDGE(r0, w0) ACC_EDGE(r1, w1) ACC_EDGE(r2, w2) ACC_EDGE(r3, w3)
    }
#pragma unroll 1
    for (; e < end; e++) {
        const float w = edge_w[e];
        const int   s = edge_src[e];
        const uint2 rr = reinterpret_cast<const uint2*>(g_xd_h + (size_t)s * FEATS)[f];
        ACC_EDGE(rr, w)
    }
#undef ACC_EDGE
    const __half2 h01 = __floats2half2_rn(acc.x, acc.y);
    const __half2 h23 = __floats2half2_rn(acc.z, acc.w);
    uint2 pack;
    pack.x = *reinterpret_cast<const uint32_t*>(&h01);
    pack.y = *reinterpret_cast<const uint32_t*>(&h23);
    __stcs(reinterpret_cast<uint2*>(g_agg_h + (size_t)node * FEATS) + f, pack);
}

// ---------------------------------------------------------------------------
// Kernel 3: fp16 mma.sync m16n8k16 GEMM, fp32 accum, ldmatrix fragments.
// 128x128 CTA tile, 8 warps (64x32 warp tiles) for 16 warps/SM of latency
// hiding, BK=64 halves, 2-stage cp.async, smem rows 144 B.
// ---------------------------------------------------------------------------
#define BKH 64                          // halves per K chunk
#define LDH 72                          // padded halves per row (144 B)
#define STAGE_H (128 * LDH)             // halves per stage per matrix
#define GEMM_SMEM_BYTES (4 * STAGE_H * 2)   // A0,A1,B0,B1 = 73728 B

__global__ void __launch_bounds__(256, 2)
gemm_mma_kernel(const float* __restrict__ bias, float* __restrict__ out) {
    extern __shared__ __half smh[];
    __half* Asm = smh;                  // [2][128][LDH]
    __half* Bsm = smh + 2 * STAGE_H;    // [2][128][LDH]

    const int tid   = threadIdx.x;
    const int wid   = tid >> 5;
    const int lane  = tid & 31;
    const int warpM = wid & 1;          // M offset 0/64
    const int warpN = wid >> 1;         // 0..3 -> N offset 0/32/64/96
    const int m0 = blockIdx.y * 128;
    const int n0 = blockIdx.x * 128;

    const uint32_t aBase = smem_u32(Asm);
    const uint32_t bBase = smem_u32(Bsm);
    const uint32_t stageBytes = STAGE_H * 2;

    // ldmatrix lane->address templates (bytes within a stage)
    const int rA   = warpM * 64 + (lane & 15);
    const int kAh  = (lane & 16) ? 8 : 0;
    const uint32_t aLane = (uint32_t)(rA * LDH + kAh) * 2;
    const int rB   = warpN * 32 + (lane & 7) + ((lane & 16) >> 1);
    const int kBh  = (lane & 8) ? 8 : 0;
    const uint32_t bLane = (uint32_t)(rB * LDH + kBh) * 2;

    float acc[4][4][4];
#pragma unroll
    for (int i = 0; i < 4; i++)
#pragma unroll
        for (int j = 0; j < 4; j++)
#pragma unroll
            for (int r = 0; r < 4; r++) acc[i][j][r] = 0.f;

    // one K chunk: 128 rows x 64 halves (128 B) per matrix; 256 threads
    auto load_tile = [&](int s, int k0) {
#pragma unroll
        for (int it = 0; it < 4; it++) {
            const int idx = it * 256 + tid;            // 0..1023
            const int row = idx >> 3, seg = idx & 7;
            cp_async16(aBase + s * stageBytes + row * 144 + seg * 16,
                       g_agg_h + (size_t)(m0 + row) * 512 + k0 + seg * 8);
        }
#pragma unroll
        for (int it = 0; it < 4; it++) {
            const int idx = it * 256 + tid;
            const int row = idx >> 3, seg = idx & 7;
            cp_async16(bBase + s * stageBytes + row * 144 + seg * 16,
                       g_Wt_h + (size_t)(n0 + row) * 512 + k0 + seg * 8);
        }
        cp_commit();
    };

    load_tile(0, 0);

    for (int c = 0; c < 8; c++) {
        const int s = c & 1;
        cp_wait<0>();
        __syncthreads();
        if (c + 1 < 8) load_tile(s ^ 1, (c + 1) * BKH);   // overlaps mma below

        const uint32_t aStage = aBase + s * stageBytes + aLane;
        const uint32_t bStage = bBase + s * stageBytes + bLane;
#pragma unroll
        for (int kk = 0; kk < 4; kk++) {
            const uint32_t kOff = kk * 32;                // 16 halves = 32 B
            uint32_t af[4][4];
#pragma unroll
            for (int mt = 0; mt < 4; mt++)
                ldsm_x4(af[mt][0], af[mt][1], af[mt][2], af[mt][3],
                        aStage + (uint32_t)(mt * 16 * LDH) * 2 + kOff);
            uint32_t bf[4][2];
#pragma unroll
            for (int ntp = 0; ntp < 2; ntp++)
                ldsm_x4(bf[2 * ntp][0], bf[2 * ntp][1],
                        bf[2 * ntp + 1][0], bf[2 * ntp + 1][1],
                        bStage + (uint32_t)(ntp * 16 * LDH) * 2 + kOff);
#pragma unroll
            for (int mt = 0; mt < 4; mt++)
#pragma unroll
                for (int nt = 0; nt < 4; nt++)
                    mma_f16(acc[mt][nt], af[mt], bf[nt]);
        }
    }

    const int qrow = lane >> 2;
    const int qcol = lane & 3;

    // epilogue: bias + relu, streaming stores
#pragma unroll
    for (int mt = 0; mt < 4; mt++) {
        const int row0 = m0 + warpM * 64 + mt * 16 + qrow;
        const int row1 = row0 + 8;
#pragma unroll
        for (int nt = 0; nt < 4; nt++) {
            const int col = n0 + warpN * 32 + nt * 8 + 2 * qcol;
            const float b0 = __ldg(bias + col);
            const float b1 = __ldg(bias + col + 1);
            if (row0 < N_NODES) {
                float2 o;
                o.x = fmaxf(acc[mt][nt][0] + b0, 0.f);
                o.y = fmaxf(acc[mt][nt][1] + b1, 0.f);
                __stcs(reinterpret_cast<float2*>(out + (size_t)row0 * 512 + col), o);
            }
            if (row1 < N_NODES) {
                float2 o;
                o.x = fmaxf(acc[mt][nt][2] + b0, 0.f);
                o.y = fmaxf(acc[mt][nt][3] + b1, 0.f);
                __stcs(reinterpret_cast<float2*>(out + (size_t)row1 * 512 + col), o);
            }
        }
    }
}

// ---------------------------------------------------------------------------
// Launch
// ---------------------------------------------------------------------------
extern "C" void kernel_launch(void* const* d_in, const int* in_sizes, int n_in,
                              void* d_out, int out_size) {
    const float* x        = (const float*)d_in[0];
    const float* edge_w   = (const float*)d_in[1];
    const float* W        = (const float*)d_in[2];
    const float* b        = (const float*)d_in[3];
    const int*   edge_src = (const int*)  d_in[4];
    const int*   edge_dst = (const int*)  d_in[5];
    float* out = (float*)d_out;

    cudaFuncSetAttribute(gemm_mma_kernel,
                         cudaFuncAttributeMaxDynamicSharedMemorySize, GEMM_SMEM_BYTES);

    transpose_W_kernel<<<dim3(16, 16), dim3(32, 8)>>>(W);
    rowptr_kernel<<<(N_EDGES + 256) / 256, 256>>>(edge_dst);
    dropout_kernel<<<(N_ELEMS / 4 + 255) / 256, 256>>>(x);
    agg_kernel<<<N_NODES, 128>>>(edge_w, edge_src);
    gemm_mma_kernel<<<dim3(4, M_TILES), 256, GEMM_SMEM_BYTES>>>(b, out);
}